// round 12
// baseline (speedup 1.0000x reference)
#include <cuda_runtime.h>
#include <math.h>

#define N 512
#define G 64                   // persistent CTAs, all co-resident
#define RPC (N / G)            // 8 rows + 8 cols per CTA
#define BLOCK 256              // 8 warps; warp w owns row/col row0+w
#define STRIDE (N + 4)         // conflict-free smem transpose stride
#define MAX_ITERS 1024
#define CONV_EPS 1e-2f
#define EXTRAP_B 0.4f          // log-space over-relaxation: rate 0.55 -> ~0.40

// Epoch-tagged vector entries: lo32 = float value, hi32 = epoch | (converged << 31).
// 8-byte aligned scalar words ONLY: the 8B ld.global.cg dependent-load poll is the
// only sync primitive validated on this chip (16B vector polls livelocked, R6/R7).
__device__ unsigned long long g_c64[N];
__device__ unsigned long long g_r64[N];

__device__ __forceinline__ unsigned long long ld64cg(const unsigned long long* p) {
    unsigned long long v;
    asm volatile("ld.global.cg.b64 %0, [%1];" : "=l"(v) : "l"(p) : "memory");
    return v;
}
__device__ __forceinline__ void st64cg(unsigned long long* p, unsigned long long v) {
    asm volatile("st.global.cg.b64 [%0], %1;" :: "l"(p), "l"(v) : "memory");
}
__device__ __forceinline__ unsigned long long pack(float v, unsigned tag) {
    return ((unsigned long long)tag << 32) | (unsigned long long)__float_as_uint(v);
}
__device__ __forceinline__ float warp_sum(float v) {
    #pragma unroll
    for (int off = 16; off > 0; off >>= 1)
        v += __shfl_xor_sync(0xffffffffu, v, off);
    return v;
}

// Warp dot of one staged matrix row (STRIDE layout) against a 512-float smem vector.
__device__ __forceinline__ float warp_dot(const float* srow, const float* s_vec, int lane) {
    const float4* sa4 = (const float4*)srow;
    const float4* sv4 = (const float4*)s_vec;
    float s0 = 0.0f, s1 = 0.0f;
    #pragma unroll
    for (int u = 0; u < 4; u += 2) {
        float4 a = sa4[lane + 32 * u],       v = sv4[lane + 32 * u];
        float4 b = sa4[lane + 32 * (u + 1)], x = sv4[lane + 32 * (u + 1)];
        s0 = fmaf(a.x, v.x, fmaf(a.y, v.y, fmaf(a.z, v.z, fmaf(a.w, v.w, s0))));
        s1 = fmaf(b.x, x.x, fmaf(b.y, x.y, fmaf(b.z, x.z, fmaf(b.w, x.w, s1))));
    }
    return warp_sum(s0 + s1);
}

__global__ void __launch_bounds__(BLOCK, 1) sinkhorn_flow8(
    const float* __restrict__ w, float* __restrict__ out)
{
    __shared__ float sA [RPC * STRIDE];   // my 8 rows of |W| (warp w writes/reads row w only)
    __shared__ float sAT[RPC * STRIDE];   // my 8 cols of |W|
    __shared__ float s_r[N];              // staged r@e
    __shared__ float s_c[N];              // staged c@(e+1)

    const int tid  = threadIdx.x;
    const int warp = tid >> 5;
    const int lane = tid & 31;
    const int row0 = blockIdx.x * RPC;
    const int my_i = row0 + warp;

    // ---- warp-per-row load: 4 x LDG.128 per lane covering the WHOLE row, then
    //      in-register rowsum -> publish r@1 BEFORE any smem/barrier (critical path).
    float r_mine;
    {
        const float4* wrow = (const float4*)(w + my_i * N);
        float4 a0 = wrow[lane], a1 = wrow[lane + 32], a2 = wrow[lane + 64], a3 = wrow[lane + 96];
        a0 = make_float4(fabsf(a0.x), fabsf(a0.y), fabsf(a0.z), fabsf(a0.w));
        a1 = make_float4(fabsf(a1.x), fabsf(a1.y), fabsf(a1.z), fabsf(a1.w));
        a2 = make_float4(fabsf(a2.x), fabsf(a2.y), fabsf(a2.z), fabsf(a2.w));
        a3 = make_float4(fabsf(a3.x), fabsf(a3.y), fabsf(a3.z), fabsf(a3.w));
        float s = ((a0.x + a0.y) + (a0.z + a0.w)) + ((a1.x + a1.y) + (a1.z + a1.w))
                + ((a2.x + a2.y) + (a2.z + a2.w)) + ((a3.x + a3.y) + (a3.z + a3.w));
        r_mine = 1.0f / warp_sum(s);
        if (lane == 0) st64cg(&g_r64[my_i], pack(r_mine, 1u));   // r@1 = 1/rowsum (c@1==1)
        // spill the abs'd row into smem (own warp's row: no barrier needed for sA)
        float4* sa4 = (float4*)(sA + warp * STRIDE);
        sa4[lane] = a0; sa4[lane + 32] = a1; sa4[lane + 64] = a2; sa4[lane + 96] = a3;
    }

    // ---- stage my 8 cols while other CTAs publish r@1 (overlap). ----
    {
        const int half = lane & 1;         // which float4 of the 8-col slab
        #pragma unroll
        for (int p = 0; p < 4; ++p) {
            int rr = warp * 64 + p * 16 + (lane >> 1);
            float4 v = *(const float4*)(w + rr * N + row0 + 4 * half);
            sAT[(4 * half + 0) * STRIDE + rr] = fabsf(v.x);
            sAT[(4 * half + 1) * STRIDE + rr] = fabsf(v.y);
            sAT[(4 * half + 2) * STRIDE + rr] = fabsf(v.z);
            sAT[(4 * half + 3) * STRIDE + rr] = fabsf(v.w);
        }
    }
    // sAT is covered by the first in-loop __syncthreads before any warp_dot on it.

    float c_prev = 1.0f;                  // previous PUBLISHED c (extrapolated)
    unsigned e = 1;
    for (;;) {
        // ---- poll r@e into s_r (8B dependent loads + done flags: validated) ----
        {
            const unsigned long long* p0 = &g_r64[tid];
            const unsigned long long* p1 = &g_r64[tid + 256];
            unsigned long long v0 = 0, v1 = 0;
            bool d0 = false, d1 = false;
            do {
                if (!d0) { v0 = ld64cg(p0); d0 = (((unsigned)(v0 >> 32)) & 0x7FFFFFFFu) == e; }
                if (!d1) { v1 = ld64cg(p1); d1 = (((unsigned)(v1 >> 32)) & 0x7FFFFFFFu) == e; }
            } while (!(d0 && d1));
            s_r[tid]       = __uint_as_float((unsigned)v0);
            s_r[tid + 256] = __uint_as_float((unsigned)v1);
        }
        __syncthreads();                                  // barrier 1 of 2

        // ---- col phase: raw chat = 1/(A^T r@e); publish log-space extrapolated c.
        //      c_pub = chat * (chat/c_prev)^B  — same fixed point, multiplicatively
        //      positive, kills the dominant convergence mode (rate 0.55 -> ~0.4). ----
        {
            float chat = 1.0f / warp_dot(sAT + warp * STRIDE, s_r, lane);
            float ratio = chat / c_prev;
            float cpub  = chat * __powf(ratio, EXTRAP_B);   // MUFU.LG2+FMUL+MUFU.EX2
            if (lane == 0) {
                unsigned conv = (fabsf(chat - c_prev) <= CONV_EPS * chat) ? 1u : 0u;
                st64cg(&g_c64[my_i], pack(cpub, (e + 1u) | (conv << 31)));
            }
            c_prev = cpub;                 // all lanes hold the same value
        }

        // ---- poll c@(e+1) into s_c; keep words for conv bits ----
        unsigned long long v0 = 0, v1 = 0;
        {
            const unsigned long long* q0 = &g_c64[tid];
            const unsigned long long* q1 = &g_c64[tid + 256];
            bool d0 = false, d1 = false;
            do {
                if (!d0) { v0 = ld64cg(q0); d0 = (((unsigned)(v0 >> 32)) & 0x7FFFFFFFu) == e + 1u; }
                if (!d1) { v1 = ld64cg(q1); d1 = (((unsigned)(v1 >> 32)) & 0x7FFFFFFFu) == e + 1u; }
            } while (!(d0 && d1));
            s_c[tid]       = __uint_as_float((unsigned)v0);
            s_c[tid + 256] = __uint_as_float((unsigned)v1);
        }
        // barrier 2 of 2: the vote IS a full barrier, and all s_c stores precede it,
        // so s_c is safe to read after. Break decision is identical data in every CTA.
        int all_conv = __syncthreads_and((int)((v0 & v1) >> 63));

        // ---- row phase (speculative): r@(e+1) = 1/(A c@(e+1)), publish.
        //      Keeps the break decision off the producer->consumer critical path. ----
        {
            r_mine = 1.0f / warp_dot(sA + warp * STRIDE, s_c, lane);
            if (lane == 0) st64cg(&g_r64[my_i], pack(r_mine, e + 1u));
        }

        if ((e >= 2u && all_conv) || e >= (unsigned)MAX_ITERS) break;
        ++e;
    }

    // ---- finalize: out[i][j] = |W|[i][j] * r@(e+1)_i * c@(e+1)_j ----
    // r_mine is the speculative r@(e+1): rows sum to exactly 1, cols within eps —
    // one extra row-normalization past the break, closer to the fixed point.
    {
        const float4* sa4 = (const float4*)(sA + warp * STRIDE);
        const float4* sv4 = (const float4*)s_c;
        float4* o4 = (float4*)(out + my_i * N);
        #pragma unroll
        for (int u = 0; u < 4; ++u) {
            float4 a = sa4[lane + 32 * u];
            float4 v = sv4[lane + 32 * u];
            o4[lane + 32 * u] = make_float4(a.x * r_mine * v.x,
                                            a.y * r_mine * v.y,
                                            a.z * r_mine * v.z,
                                            a.w * r_mine * v.w);
        }
    }
}

extern "C" void kernel_launch(void* const* d_in, const int* in_sizes, int n_in,
                              void* d_out, int out_size) {
    const float* w = (const float*)d_in[0];
    float* out = (float*)d_out;
    sinkhorn_flow8<<<G, BLOCK>>>(w, out);
}

// round 13
// speedup vs baseline: 1.3661x; 1.3661x over previous
#include <cuda_runtime.h>
#include <math.h>

#define N 512
#define G 64                   // persistent CTAs, all co-resident
#define RPC (N / G)            // 8 rows + 8 cols per CTA
#define BLOCK 256              // 8 warps; warp w owns row/col row0+w
#define STRIDE (N + 4)         // conflict-free smem transpose stride
#define MAX_ITERS 1024
#define CONV_EPS 1e-2f

// Epoch-tagged vector entries: lo32 = float value, hi32 = epoch | (converged << 31).
// 8-byte aligned scalar words ONLY: the 8B ld.global.cg dependent-load poll is the
// only sync primitive validated on this chip (16B vector polls livelocked, R6/R7).
__device__ unsigned long long g_c64[N];
__device__ unsigned long long g_r64[N];

__device__ __forceinline__ unsigned long long ld64cg(const unsigned long long* p) {
    unsigned long long v;
    asm volatile("ld.global.cg.b64 %0, [%1];" : "=l"(v) : "l"(p) : "memory");
    return v;
}
__device__ __forceinline__ void st64cg(unsigned long long* p, unsigned long long v) {
    asm volatile("st.global.cg.b64 [%0], %1;" :: "l"(p), "l"(v) : "memory");
}
__device__ __forceinline__ unsigned long long pack(float v, unsigned tag) {
    return ((unsigned long long)tag << 32) | (unsigned long long)__float_as_uint(v);
}
__device__ __forceinline__ float warp_sum(float v) {
    #pragma unroll
    for (int off = 16; off > 0; off >>= 1)
        v += __shfl_xor_sync(0xffffffffu, v, off);
    return v;
}

// Warp dot of one staged matrix row (STRIDE layout) against a 512-float smem vector.
// 4 independent accumulators: FMA dependency chain ~16cyc instead of 32.
__device__ __forceinline__ float warp_dot(const float* srow, const float* s_vec, int lane) {
    const float4* sa4 = (const float4*)srow;
    const float4* sv4 = (const float4*)s_vec;
    float s0, s1, s2, s3;
    {
        float4 a = sa4[lane],      v = sv4[lane];
        s0 = fmaf(a.x, v.x, fmaf(a.y, v.y, fmaf(a.z, v.z, a.w * v.w)));
    }
    {
        float4 a = sa4[lane + 32], v = sv4[lane + 32];
        s1 = fmaf(a.x, v.x, fmaf(a.y, v.y, fmaf(a.z, v.z, a.w * v.w)));
    }
    {
        float4 a = sa4[lane + 64], v = sv4[lane + 64];
        s2 = fmaf(a.x, v.x, fmaf(a.y, v.y, fmaf(a.z, v.z, a.w * v.w)));
    }
    {
        float4 a = sa4[lane + 96], v = sv4[lane + 96];
        s3 = fmaf(a.x, v.x, fmaf(a.y, v.y, fmaf(a.z, v.z, a.w * v.w)));
    }
    return warp_sum((s0 + s1) + (s2 + s3));
}

__global__ void __launch_bounds__(BLOCK, 1) sinkhorn_flow9(
    const float* __restrict__ w, float* __restrict__ out)
{
    __shared__ float sA [RPC * STRIDE];   // my 8 rows of |W| (warp w writes/reads row w only)
    __shared__ float sAT[RPC * STRIDE];   // my 8 cols of |W|
    __shared__ float s_r[N];              // staged r@e
    __shared__ float s_c[N];              // staged c@(e+1)

    const int tid  = threadIdx.x;
    const int warp = tid >> 5;
    const int lane = tid & 31;
    const int row0 = blockIdx.x * RPC;
    const int my_i = row0 + warp;

    // ---- warp-per-row load: 4 x LDG.128 per lane covering the WHOLE row, then
    //      in-register rowsum -> publish r@1 BEFORE any smem/barrier (critical path).
    float r_mine;
    {
        const float4* wrow = (const float4*)(w + my_i * N);
        float4 a0 = wrow[lane], a1 = wrow[lane + 32], a2 = wrow[lane + 64], a3 = wrow[lane + 96];
        a0 = make_float4(fabsf(a0.x), fabsf(a0.y), fabsf(a0.z), fabsf(a0.w));
        a1 = make_float4(fabsf(a1.x), fabsf(a1.y), fabsf(a1.z), fabsf(a1.w));
        a2 = make_float4(fabsf(a2.x), fabsf(a2.y), fabsf(a2.z), fabsf(a2.w));
        a3 = make_float4(fabsf(a3.x), fabsf(a3.y), fabsf(a3.z), fabsf(a3.w));
        float s = (((a0.x + a0.y) + (a0.z + a0.w)) + ((a1.x + a1.y) + (a1.z + a1.w)))
                + (((a2.x + a2.y) + (a2.z + a2.w)) + ((a3.x + a3.y) + (a3.z + a3.w)));
        r_mine = 1.0f / warp_sum(s);
        if (lane == 0) st64cg(&g_r64[my_i], pack(r_mine, 1u));   // r@1 = 1/rowsum (c@1==1)
        // spill the abs'd row into smem (own warp's row: no barrier needed for sA)
        float4* sa4 = (float4*)(sA + warp * STRIDE);
        sa4[lane] = a0; sa4[lane + 32] = a1; sa4[lane + 64] = a2; sa4[lane + 96] = a3;
    }

    // ---- stage my 8 cols while other CTAs publish r@1 (overlap). ----
    {
        const int half = lane & 1;         // which float4 of the 8-col slab
        #pragma unroll
        for (int p = 0; p < 4; ++p) {
            int rr = warp * 64 + p * 16 + (lane >> 1);
            float4 v = *(const float4*)(w + rr * N + row0 + 4 * half);
            sAT[(4 * half + 0) * STRIDE + rr] = fabsf(v.x);
            sAT[(4 * half + 1) * STRIDE + rr] = fabsf(v.y);
            sAT[(4 * half + 2) * STRIDE + rr] = fabsf(v.z);
            sAT[(4 * half + 3) * STRIDE + rr] = fabsf(v.w);
        }
    }
    // sAT is covered by the first in-loop __syncthreads before any warp_dot on it.

    float c_prev = 1.0f;
    unsigned e = 1;
    for (;;) {
        // ---- poll r@e into s_r (8B dependent loads + done flags: validated) ----
        {
            const unsigned long long* p0 = &g_r64[tid];
            const unsigned long long* p1 = &g_r64[tid + 256];
            unsigned long long v0 = 0, v1 = 0;
            bool d0 = false, d1 = false;
            do {
                if (!d0) { v0 = ld64cg(p0); d0 = (((unsigned)(v0 >> 32)) & 0x7FFFFFFFu) == e; }
                if (!d1) { v1 = ld64cg(p1); d1 = (((unsigned)(v1 >> 32)) & 0x7FFFFFFFu) == e; }
            } while (!(d0 && d1));
            s_r[tid]       = __uint_as_float((unsigned)v0);
            s_r[tid + 256] = __uint_as_float((unsigned)v1);
        }
        __syncthreads();                                  // barrier 1 of 2

        // ---- col phase: c@(e+1) = 1/(A^T r@e), publish with conv bit ----
        {
            float c_new = 1.0f / warp_dot(sAT + warp * STRIDE, s_r, lane);
            if (lane == 0) {
                unsigned conv = (fabsf(c_new - c_prev) <= CONV_EPS * fabsf(c_new)) ? 1u : 0u;
                st64cg(&g_c64[my_i], pack(c_new, (e + 1u) | (conv << 31)));
            }
            c_prev = c_new;
        }

        // ---- poll c@(e+1) into s_c; keep words for conv bits ----
        unsigned long long v0 = 0, v1 = 0;
        {
            const unsigned long long* q0 = &g_c64[tid];
            const unsigned long long* q1 = &g_c64[tid + 256];
            bool d0 = false, d1 = false;
            do {
                if (!d0) { v0 = ld64cg(q0); d0 = (((unsigned)(v0 >> 32)) & 0x7FFFFFFFu) == e + 1u; }
                if (!d1) { v1 = ld64cg(q1); d1 = (((unsigned)(v1 >> 32)) & 0x7FFFFFFFu) == e + 1u; }
            } while (!(d0 && d1));
            s_c[tid]       = __uint_as_float((unsigned)v0);
            s_c[tid + 256] = __uint_as_float((unsigned)v1);
        }
        // barrier 2 of 2: the vote IS a full barrier, and all s_c stores precede it,
        // so s_c is safe to read after. Break decision is identical data in every CTA.
        int all_conv = __syncthreads_and((int)((v0 & v1) >> 63));

        // ---- row phase (speculative): r@(e+1) = 1/(A c@(e+1)), publish.
        //      Keeps the break decision off the producer->consumer critical path.
        //      Final-epoch extra publish is unconsumed this run; on graph replay
        //      stale tags carry bit-identical values (deterministic trajectory). ----
        {
            r_mine = 1.0f / warp_dot(sA + warp * STRIDE, s_c, lane);
            if (lane == 0) st64cg(&g_r64[my_i], pack(r_mine, e + 1u));
        }

        if ((e >= 2u && all_conv) || e >= (unsigned)MAX_ITERS) break;
        ++e;
    }

    // ---- finalize: out[i][j] = |W|[i][j] * r@(e+1)_i * c@(e+1)_j ----
    // r_mine is the speculative r@(e+1): rows sum to exactly 1, cols within eps —
    // one extra row-normalization past the break, closer to the fixed point.
    {
        const float4* sa4 = (const float4*)(sA + warp * STRIDE);
        const float4* sv4 = (const float4*)s_c;
        float4* o4 = (float4*)(out + my_i * N);
        #pragma unroll
        for (int u = 0; u < 4; ++u) {
            float4 a = sa4[lane + 32 * u];
            float4 v = sv4[lane + 32 * u];
            o4[lane + 32 * u] = make_float4(a.x * r_mine * v.x,
                                            a.y * r_mine * v.y,
                                            a.z * r_mine * v.z,
                                            a.w * r_mine * v.w);
        }
    }
}

extern "C" void kernel_launch(void* const* d_in, const int* in_sizes, int n_in,
                              void* d_out, int out_size) {
    const float* w = (const float*)d_in[0];
    float* out = (float*)d_out;
    sinkhorn_flow9<<<G, BLOCK>>>(w, out);
}